// round 1
// baseline (speedup 1.0000x reference)
#include <cuda_runtime.h>
#include <cstdint>

#define Nn 50000
#define Ee 800000
#define Rr 8
#define Fd 128
#define Hd 128
#define Cc 64
#define RH (Rr * Hd)   // 1024

// ---------------- device scratch (static, zero-init, no allocs) ----------------
__device__ float    g_xr[(size_t)Nn * RH];     // 204.8 MB per-relation transforms
__device__ float    g_hA[Nn * Hd];
__device__ float    g_hB[Nn * Hd];
__device__ float    g_acc[Nn * Hd];
__device__ float    g_qx[Nn * Rr];
__device__ float    g_kx[Nn * Rr];
__device__ float    g_alpha[Ee];
__device__ unsigned g_mEnc[Nn];
__device__ float    g_denom[Nn];
__device__ float    g_Wt[Fd * RH];             // W transposed to [F, R*H]
__device__ float    g_Wq[Rr * Fd];
__device__ float    g_Wk[Rr * Fd];
__device__ int      g_src[Ee];
__device__ int      g_dst[Ee];
__device__ int      g_et[Ee];
__device__ int      g_is64;

// ---------------- helpers ----------------
__device__ __forceinline__ unsigned encf(float f) {
    unsigned u = __float_as_uint(f);
    return (u & 0x80000000u) ? ~u : (u | 0x80000000u);
}
__device__ __forceinline__ float decf(unsigned u) {
    return (u & 0x80000000u) ? __uint_as_float(u & 0x7FFFFFFFu)
                             : __uint_as_float(~u);
}

// ---------------- dtype detect + edge conversion ----------------
__global__ void detect_kernel(const unsigned* __restrict__ ei) {
    if (threadIdx.x == 0 && blockIdx.x == 0) {
        int zeros = 0;
        for (int i = 0; i < 128; i++)
            if (ei[2 * i + 1] == 0u) zeros++;
        g_is64 = (zeros == 128) ? 1 : 0;   // int64 little-endian: hi words all 0
    }
}

__global__ void convert_kernel(const void* __restrict__ ei, const void* __restrict__ et) {
    int e = blockIdx.x * blockDim.x + threadIdx.x;
    if (e >= Ee) return;
    if (g_is64) {
        const long long* p = (const long long*)ei;
        g_src[e] = (int)p[e];
        g_dst[e] = (int)p[Ee + e];
        g_et[e]  = (int)((const long long*)et)[e];
    } else {
        const int* p = (const int*)ei;
        g_src[e] = p[e];
        g_dst[e] = p[Ee + e];
        g_et[e]  = ((const int*)et)[e];
    }
}

// ---------------- per-layer weight prep ----------------
// Wq[r,f] = sum_h W[r,f,h]*q[h]; Wk likewise. One warp per (r,f).
__global__ void wqk_kernel(const float* __restrict__ W,
                           const float* __restrict__ q,
                           const float* __restrict__ k) {
    int warp = (blockIdx.x * blockDim.x + threadIdx.x) >> 5;
    int lane = threadIdx.x & 31;
    if (warp >= Rr * Fd) return;
    const float* wrow = W + (size_t)warp * Hd;
    float sq = 0.f, sk = 0.f;
#pragma unroll
    for (int j = 0; j < 4; j++) {
        float wv = wrow[lane + 32 * j];
        sq += wv * q[lane + 32 * j];
        sk += wv * k[lane + 32 * j];
    }
#pragma unroll
    for (int o = 16; o; o >>= 1) {
        sq += __shfl_xor_sync(0xffffffffu, sq, o);
        sk += __shfl_xor_sync(0xffffffffu, sk, o);
    }
    if (lane == 0) { g_Wq[warp] = sq; g_Wk[warp] = sk; }
}

// Wt[f*RH + r*Hd + h] = W[r*Fd*Hd + f*Hd + h]
__global__ void transpose_kernel(const float* __restrict__ W) {
    int idx = blockIdx.x * blockDim.x + threadIdx.x;
    if (idx >= Rr * Fd * Hd) return;
    int h = idx & 127;
    int f = (idx >> 7) & 127;
    int r = idx >> 14;
    g_Wt[f * RH + r * Hd + h] = W[idx];
}

// ---------------- SGEMM: g_xr[N,1024] = xin[N,128] @ g_Wt[128,1024] ----------------
#define GBM 128
#define GBN 128
#define GBK 16
__global__ __launch_bounds__(256) void sgemm_kernel(const float* __restrict__ A, int M) {
    __shared__ __align__(16) float As[GBK][GBM];
    __shared__ __align__(16) float Bs[GBK][GBN];
    int tid = threadIdx.x;
    int tx = tid & 15, ty = tid >> 4;
    int row0 = blockIdx.y * GBM, col0 = blockIdx.x * GBN;
    float acc[8][8] = {};
    for (int k0 = 0; k0 < Fd; k0 += GBK) {
        // A tile: 128 rows x 16 k  (2048 floats, 2 float4 per thread), transposed store
#pragma unroll
        for (int l = 0; l < 2; l++) {
            int idx = tid + l * 256;      // 0..511
            int r = idx >> 2;             // 0..127
            int c4 = idx & 3;             // 0..3
            float4 v = make_float4(0.f, 0.f, 0.f, 0.f);
            int grow = row0 + r;
            if (grow < M) v = *(const float4*)&A[(size_t)grow * Fd + k0 + c4 * 4];
            As[c4 * 4 + 0][r] = v.x;
            As[c4 * 4 + 1][r] = v.y;
            As[c4 * 4 + 2][r] = v.z;
            As[c4 * 4 + 3][r] = v.w;
        }
        // B tile: 16 k x 128 cols
#pragma unroll
        for (int l = 0; l < 2; l++) {
            int idx = tid + l * 256;      // 0..511
            int kk = idx >> 5;            // 0..15
            int c4 = idx & 31;            // 0..31
            *(float4*)&Bs[kk][c4 * 4] =
                *(const float4*)&g_Wt[(size_t)(k0 + kk) * RH + col0 + c4 * 4];
        }
        __syncthreads();
#pragma unroll
        for (int kk = 0; kk < GBK; kk++) {
            float a[8], b[8];
            *(float4*)&a[0] = *(float4*)&As[kk][ty * 8];
            *(float4*)&a[4] = *(float4*)&As[kk][ty * 8 + 4];
            *(float4*)&b[0] = *(float4*)&Bs[kk][tx * 8];
            *(float4*)&b[4] = *(float4*)&Bs[kk][tx * 8 + 4];
#pragma unroll
            for (int i = 0; i < 8; i++)
#pragma unroll
                for (int j = 0; j < 8; j++)
                    acc[i][j] = fmaf(a[i], b[j], acc[i][j]);
        }
        __syncthreads();
    }
#pragma unroll
    for (int i = 0; i < 8; i++) {
        int grow = row0 + ty * 8 + i;
        if (grow < M) {
#pragma unroll
            for (int j4 = 0; j4 < 2; j4++) {
                float4 v = make_float4(acc[i][j4 * 4 + 0], acc[i][j4 * 4 + 1],
                                       acc[i][j4 * 4 + 2], acc[i][j4 * 4 + 3]);
                *(float4*)&g_xr[(size_t)grow * RH + col0 + tx * 8 + j4 * 4] = v;
            }
        }
    }
}

// ---------------- attention scores qx,kx [N,R] ----------------
__global__ void qxkx_kernel(const float* __restrict__ xin) {
    int t = blockIdx.x * blockDim.x + threadIdx.x;
    if (t >= Nn * Rr) return;
    int n = t >> 3, r = t & 7;
    const float* xrow = xin + (size_t)n * Fd;
    const float* wq = g_Wq + r * Fd;
    const float* wk = g_Wk + r * Fd;
    float sq = 0.f, sk = 0.f;
#pragma unroll 32
    for (int f = 0; f < Fd; f++) {
        float xv = __ldg(xrow + f);
        sq = fmaf(xv, __ldg(wq + f), sq);
        sk = fmaf(xv, __ldg(wk + f), sk);
    }
    g_qx[t] = sq;
    g_kx[t] = sk;
}

// ---------------- softmax init + edge passes ----------------
__global__ void init_kernel() {
    int idx = blockIdx.x * blockDim.x + threadIdx.x;
    if (idx < Nn * Hd) g_acc[idx] = 0.f;
    if (idx < Nn) { g_mEnc[idx] = 0x007FFFFFu; g_denom[idx] = 0.f; }  // enc(-inf)
}

__global__ void edge1_kernel() {
    int e = blockIdx.x * blockDim.x + threadIdx.x;
    if (e >= Ee) return;
    int s = g_src[e], d = g_dst[e], t = g_et[e];
    float a = g_qx[d * Rr + t] + g_kx[s * Rr + t];
    a = (a >= 0.f) ? a : 0.2f * a;
    g_alpha[e] = a;
    atomicMax(&g_mEnc[d], encf(a));
}

__global__ void edge2_kernel() {
    int e = blockIdx.x * blockDim.x + threadIdx.x;
    if (e >= Ee) return;
    int d = g_dst[e];
    float m = decf(g_mEnc[d]);
    float ew = expf(g_alpha[e] - m);
    g_alpha[e] = ew;
    atomicAdd(&g_denom[d], ew);
}

// one warp per edge: acc[dst] += w * xr[src, et, :]  (vector reductions)
__global__ void edge3_kernel() {
    int gtid = blockIdx.x * blockDim.x + threadIdx.x;
    int e = gtid >> 5;
    if (e >= Ee) return;
    int lane = gtid & 31;
    int s = g_src[e], d = g_dst[e], t = g_et[e];
    float w = g_alpha[e] / g_denom[d];
    const float4* row = (const float4*)(g_xr + (size_t)s * RH + t * Hd);
    float4 v = row[lane];
    float4* o = (float4*)(g_acc + (size_t)d * Hd) + lane;
    asm volatile("red.global.add.v4.f32 [%0], {%1, %2, %3, %4};"
                 :: "l"(o), "f"(v.x * w), "f"(v.y * w), "f"(v.z * w), "f"(v.w * w)
                 : "memory");
}

__global__ void bias_relu_kernel(const float* __restrict__ b, float* __restrict__ hout) {
    int idx = blockIdx.x * blockDim.x + threadIdx.x;
    if (idx >= Nn * Hd) return;
    float v = g_acc[idx] + b[idx & 127];
    hout[idx] = v > 0.f ? v : 0.f;
}

// ---------------- final linear + log_softmax ----------------
__global__ __launch_bounds__(256) void final_kernel(const float* __restrict__ h,
                                                    const float* __restrict__ lw,
                                                    const float* __restrict__ lb,
                                                    float* __restrict__ out) {
    __shared__ float sh[8][Hd];
    int tid = threadIdx.x;
    int nodeBase = blockIdx.x * 8;
#pragma unroll
    for (int l = 0; l < 4; l++) {
        int idx = tid + l * 256;
        sh[idx >> 7][idx & 127] = h[(size_t)nodeBase * Hd + idx];
    }
    __syncthreads();
    int w = tid >> 5, lane = tid & 31;
    int n = nodeBase + w;
    float a0 = lb[lane], a1 = lb[lane + 32];
#pragma unroll 16
    for (int f = 0; f < Hd; f++) {
        float hv = sh[w][f];
        a0 = fmaf(hv, lw[f * Cc + lane], a0);
        a1 = fmaf(hv, lw[f * Cc + lane + 32], a1);
    }
    float mx = fmaxf(a0, a1);
#pragma unroll
    for (int o = 16; o; o >>= 1) mx = fmaxf(mx, __shfl_xor_sync(0xffffffffu, mx, o));
    float s = expf(a0 - mx) + expf(a1 - mx);
#pragma unroll
    for (int o = 16; o; o >>= 1) s += __shfl_xor_sync(0xffffffffu, s, o);
    float lse = mx + logf(s);
    out[(size_t)n * Cc + lane]      = a0 - lse;
    out[(size_t)n * Cc + lane + 32] = a1 - lse;
}

// ---------------- host orchestration ----------------
static void run_layer(const float* xin, const float* W, const float* q,
                      const float* k, const float* b, float* hout) {
    wqk_kernel<<<(Rr * Fd * 32 + 255) / 256, 256>>>(W, q, k);
    transpose_kernel<<<(Rr * Fd * Hd + 255) / 256, 256>>>(W);
    dim3 gg(RH / GBN, (Nn + GBM - 1) / GBM);
    sgemm_kernel<<<gg, 256>>>(xin, Nn);
    qxkx_kernel<<<(Nn * Rr + 255) / 256, 256>>>(xin);
    init_kernel<<<(Nn * Hd + 255) / 256, 256>>>();
    edge1_kernel<<<(Ee + 255) / 256, 256>>>();
    edge2_kernel<<<(Ee + 255) / 256, 256>>>();
    edge3_kernel<<<(Ee * 32 + 255) / 256, 256>>>();
    bias_relu_kernel<<<(Nn * Hd + 255) / 256, 256>>>(b, hout);
}

extern "C" void kernel_launch(void* const* d_in, const int* in_sizes, int n_in,
                              void* d_out, int out_size) {
    const float* x     = (const float*)d_in[0];
    const void*  ei    = d_in[1];
    const void*  et    = d_in[2];
    const float* W1    = (const float*)d_in[3];
    const float* q1    = (const float*)d_in[4];
    const float* k1    = (const float*)d_in[5];
    const float* b1    = (const float*)d_in[6];
    const float* W2    = (const float*)d_in[7];
    const float* q2    = (const float*)d_in[8];
    const float* k2    = (const float*)d_in[9];
    const float* b2    = (const float*)d_in[10];
    const float* W3    = (const float*)d_in[11];
    const float* q3    = (const float*)d_in[12];
    const float* k3    = (const float*)d_in[13];
    const float* b3    = (const float*)d_in[14];
    const float* lin_w = (const float*)d_in[15];
    const float* lin_b = (const float*)d_in[16];

    float *hA = nullptr, *hB = nullptr;
    cudaGetSymbolAddress((void**)&hA, g_hA);
    cudaGetSymbolAddress((void**)&hB, g_hB);

    detect_kernel<<<1, 32>>>((const unsigned*)ei);
    convert_kernel<<<(Ee + 255) / 256, 256>>>(ei, et);

    run_layer(x,  W1, q1, k1, b1, hA);
    run_layer(hA, W2, q2, k2, b2, hB);
    run_layer(hB, W3, q3, k3, b3, hA);

    final_kernel<<<Nn / 8, 256>>>(hA, lin_w, lin_b, (float*)d_out);
}

// round 3
// speedup vs baseline: 1.7194x; 1.7194x over previous
#include <cuda_runtime.h>
#include <cuda_bf16.h>
#include <cstdint>

#define Nn 50000
#define Ee 800000
#define Rr 8
#define Fd 128
#define Hd 128
#define Cc 64
#define RH (Rr * Hd)   // 1024

// ---------------- device scratch ----------------
__device__ float         g_xr[(size_t)Nn * RH];
__device__ float         g_hA[Nn * Hd];
__device__ float         g_hB[Nn * Hd];
__device__ float         g_acc[Nn * Hd];
__device__ float         g_qx[Nn * Rr];
__device__ float         g_kx[Nn * Rr];
__device__ float         g_alpha[Ee];
__device__ unsigned      g_mEnc[Nn];
__device__ float         g_denom[Nn];
__device__ __nv_bfloat16 g_Wbh[RH * Fd];   // B matrix [n=r*H+h][f], hi part
__device__ __nv_bfloat16 g_Wbl[RH * Fd];   // lo part
__device__ int           g_src[Ee];
__device__ int           g_dst[Ee];
__device__ int           g_et[Ee];
__device__ int           g_is64;

// ---------------- helpers ----------------
__device__ __forceinline__ unsigned encf(float f) {
    unsigned u = __float_as_uint(f);
    return (u & 0x80000000u) ? ~u : (u | 0x80000000u);
}
__device__ __forceinline__ float decf(unsigned u) {
    return (u & 0x80000000u) ? __uint_as_float(u & 0x7FFFFFFFu)
                             : __uint_as_float(~u);
}
__device__ __forceinline__ uint32_t smem_u32(const void* p) {
    uint32_t a;
    asm("{ .reg .u64 t; cvta.to.shared.u64 t, %1; cvt.u32.u64 %0, t; }" : "=r"(a) : "l"(p));
    return a;
}
__device__ __forceinline__ void ldsm_x4(uint32_t* r, uint32_t addr) {
    asm volatile("ldmatrix.sync.aligned.m8n8.x4.shared.b16 {%0,%1,%2,%3}, [%4];"
                 : "=r"(r[0]), "=r"(r[1]), "=r"(r[2]), "=r"(r[3]) : "r"(addr));
}
__device__ __forceinline__ void mma_bf16(float* c, const uint32_t* a, uint32_t b0, uint32_t b1) {
    asm volatile(
        "mma.sync.aligned.m16n8k16.row.col.f32.bf16.bf16.f32 "
        "{%0,%1,%2,%3}, {%4,%5,%6,%7}, {%8,%9}, {%0,%1,%2,%3};"
        : "+f"(c[0]), "+f"(c[1]), "+f"(c[2]), "+f"(c[3])
        : "r"(a[0]), "r"(a[1]), "r"(a[2]), "r"(a[3]), "r"(b0), "r"(b1));
}

// ---------------- dtype detect + edge conversion ----------------
__global__ void detect_kernel(const unsigned* __restrict__ ei) {
    if (threadIdx.x == 0 && blockIdx.x == 0) {
        int zeros = 0;
        for (int i = 0; i < 128; i++)
            if (ei[2 * i + 1] == 0u) zeros++;
        g_is64 = (zeros == 128) ? 1 : 0;
    }
}

__global__ void convert_kernel(const void* __restrict__ ei, const void* __restrict__ et) {
    int e = blockIdx.x * blockDim.x + threadIdx.x;
    if (e >= Ee) return;
    if (g_is64) {
        const long long* p = (const long long*)ei;
        g_src[e] = (int)p[e];
        g_dst[e] = (int)p[Ee + e];
        g_et[e]  = (int)((const long long*)et)[e];
    } else {
        const int* p = (const int*)ei;
        g_src[e] = p[e];
        g_dst[e] = p[Ee + e];
        g_et[e]  = ((const int*)et)[e];
    }
}

// ---------------- weight prep: W[r,f,h] -> Wb[n=r*H+h, f] bf16 hi/lo ----------------
__global__ void wprep_kernel(const float* __restrict__ W) {
    int idx = blockIdx.x * blockDim.x + threadIdx.x;     // over RH*Fd
    if (idx >= RH * Fd) return;
    int f = idx & 127;
    int n = idx >> 7;               // r*128 + h
    int h = n & 127;
    int r = n >> 7;
    float v = W[(size_t)r * Fd * Hd + (size_t)f * Hd + h];
    __nv_bfloat16 hi = __float2bfloat16(v);
    __nv_bfloat16 lo = __float2bfloat16(v - __bfloat162float(hi));
    g_Wbh[idx] = hi;
    g_Wbl[idx] = lo;
}

// ---------------- mma.sync bf16 3-pass GEMM ----------------
// C[128 rows][128 cols of relation r] = x[rows][128] @ Wb[r]^T, fp32-accurate.
// Smem: 4 operand buffers of 128 rows x 64 k bf16, padded stride 72 elems (144B).
#define KC 64
#define SSTR 72                       // bf16 elems per row (144 B, 16B-aligned, conflict-free)
#define BUF_BYTES (128 * SSTR * 2)    // 18432
#define OFF_AH 0
#define OFF_AL BUF_BYTES
#define OFF_BH (2 * BUF_BYTES)
#define OFF_BL (3 * BUF_BYTES)
#define SM_TOTAL (4 * BUF_BYTES)      // 73728; stage (128x132 f32 = 67584) reuses it

__global__ __launch_bounds__(256) void gemm_mma_kernel(const float* __restrict__ A,
                                                       const float* __restrict__ qv,
                                                       const float* __restrict__ kv) {
    extern __shared__ __align__(16) char smem[];
    const int tid = threadIdx.x, wid = tid >> 5, lane = tid & 31;
    const int r = blockIdx.x;                 // relation
    const int row0 = blockIdx.y * 128;
    const int wr = wid >> 2, wc = wid & 3;    // warp 2x4 grid: rows 64*wr, cols 32*wc
    const uint32_t sb = smem_u32(smem);

    float acc[4][4][4] = {};                  // [mt][nt][frag]

#pragma unroll
    for (int kc = 0; kc < 2; kc++) {
        if (kc) __syncthreads();
        const int kbase = kc * KC;
        // ---- load A chunk: 128 rows x 64 k fp32 -> bf16 hi/lo ----
#pragma unroll
        for (int i = 0; i < 8; i++) {
            int cid = tid + i * 256;          // 0..2047 float4s
            int row = cid >> 4;
            int c4  = (cid & 15) * 4;
            float4 v = make_float4(0.f, 0.f, 0.f, 0.f);
            int gr = row0 + row;
            if (gr < Nn) v = *(const float4*)&A[(size_t)gr * Fd + kbase + c4];
            __nv_bfloat16 h0 = __float2bfloat16(v.x), h1 = __float2bfloat16(v.y);
            __nv_bfloat16 h2 = __float2bfloat16(v.z), h3 = __float2bfloat16(v.w);
            __nv_bfloat16 l0 = __float2bfloat16(v.x - __bfloat162float(h0));
            __nv_bfloat16 l1 = __float2bfloat16(v.y - __bfloat162float(h1));
            __nv_bfloat16 l2 = __float2bfloat16(v.z - __bfloat162float(h2));
            __nv_bfloat16 l3 = __float2bfloat16(v.w - __bfloat162float(h3));
            __nv_bfloat162 ph0, ph1, pl0, pl1;
            ph0.x = h0; ph0.y = h1; ph1.x = h2; ph1.y = h3;
            pl0.x = l0; pl0.y = l1; pl1.x = l2; pl1.y = l3;
            uint2 sh, sl;
            sh.x = *(uint32_t*)&ph0; sh.y = *(uint32_t*)&ph1;
            sl.x = *(uint32_t*)&pl0; sl.y = *(uint32_t*)&pl1;
            uint32_t off = (uint32_t)(row * SSTR + c4) * 2;
            *(uint2*)(smem + OFF_AH + off) = sh;
            *(uint2*)(smem + OFF_AL + off) = sl;
        }
        // ---- load B chunk: 128 rows (h) x 64 k bf16 hi/lo ----
#pragma unroll
        for (int i = 0; i < 4; i++) {
            int cid = tid + i * 256;          // 0..1023 uint4s (8 bf16)
            int row = cid >> 3;
            int k0  = (cid & 7) * 8;
            size_t gidx = (size_t)(r * 128 + row) * Fd + kbase + k0;
            uint4 vh = *(const uint4*)&g_Wbh[gidx];
            uint4 vl = *(const uint4*)&g_Wbl[gidx];
            uint32_t off = (uint32_t)(row * SSTR + k0) * 2;
            *(uint4*)(smem + OFF_BH + off) = vh;
            *(uint4*)(smem + OFF_BL + off) = vl;
        }
        __syncthreads();

        // ---- compute: 4 k16-steps x 3 precision passes ----
#pragma unroll
        for (int ks = 0; ks < 4; ks++) {
            const int k0 = ks * 16;
            const uint32_t lrow = lane & 15;
            const uint32_t lcol = (k0 + ((lane >> 4) << 3)) * 2;   // byte col
            uint32_t ah[4][4], al[4][4], bh[2][4], bl[2][4];
#pragma unroll
            for (int mt = 0; mt < 4; mt++) {
                uint32_t base = sb + (wr * 64 + mt * 16 + lrow) * (SSTR * 2) + lcol;
                ldsm_x4(ah[mt], base + OFF_AH);
                ldsm_x4(al[mt], base + OFF_AL);
            }
#pragma unroll
            for (int p = 0; p < 2; p++) {
                uint32_t base = sb + (wc * 32 + p * 16 + lrow) * (SSTR * 2) + lcol;
                ldsm_x4(bh[p], base + OFF_BH);
                ldsm_x4(bl[p], base + OFF_BL);
            }
#pragma unroll
            for (int mt = 0; mt < 4; mt++)
#pragma unroll
                for (int p = 0; p < 2; p++)
#pragma unroll
                    for (int q = 0; q < 2; q++) {
                        float* c = acc[mt][p * 2 + q];
                        mma_bf16(c, ah[mt], bh[p][q], bh[p][q + 2]);   // hi*hi
                        mma_bf16(c, ah[mt], bl[p][q], bl[p][q + 2]);   // hi*lo
                        mma_bf16(c, al[mt], bh[p][q], bh[p][q + 2]);   // lo*hi
                    }
        }
    }
    __syncthreads();

    // ---- stage accumulators to smem (reuse operand buffers) ----
    float (*stage)[132] = (float(*)[132])smem;
#pragma unroll
    for (int mt = 0; mt < 4; mt++)
#pragma unroll
        for (int nt = 0; nt < 4; nt++) {
            int rr = wr * 64 + mt * 16 + (lane >> 2);
            int cc = wc * 32 + nt * 8 + (lane & 3) * 2;
            stage[rr][cc]     = acc[mt][nt][0];
            stage[rr][cc + 1] = acc[mt][nt][1];
            stage[rr + 8][cc]     = acc[mt][nt][2];
            stage[rr + 8][cc + 1] = acc[mt][nt][3];
        }
    __syncthreads();

    // ---- fused qx/kx: warp w handles rows 16w..16w+15 (full 128-h dot -> plain store) ----
    {
        float4 q4 = *(const float4*)&qv[lane * 4];
        float4 k4 = *(const float4*)&kv[lane * 4];
#pragma unroll
        for (int i = 0; i < 16; i++) {
            int rr = wid * 16 + i;
            float4 v = *(const float4*)&stage[rr][lane * 4];
            float qs = v.x * q4.x + v.y * q4.y + v.z * q4.z + v.w * q4.w;
            float ks = v.x * k4.x + v.y * k4.y + v.z * k4.z + v.w * k4.w;
#pragma unroll
            for (int o = 16; o; o >>= 1) {
                qs += __shfl_xor_sync(0xffffffffu, qs, o);
                ks += __shfl_xor_sync(0xffffffffu, ks, o);
            }
            int node = row0 + rr;
            if (lane == 0 && node < Nn) {
                g_qx[node * Rr + r] = qs;
                g_kx[node * Rr + r] = ks;
            }
        }
    }

    // ---- coalesced xr store ----
#pragma unroll
    for (int i = 0; i < 16; i++) {
        int cid = tid + i * 256;              // 0..4095 float4s (128 rows x 32)
        int row = cid >> 5;
        int c4  = (cid & 31) * 4;
        int node = row0 + row;
        if (node < Nn) {
            float4 v = *(const float4*)&stage[row][c4];
            *(float4*)&g_xr[(size_t)node * RH + r * Hd + c4] = v;
        }
    }
}

// ---------------- softmax init + edge passes ----------------
__global__ void init_kernel() {
    int idx = blockIdx.x * blockDim.x + threadIdx.x;
    if (idx < Nn * Hd) g_acc[idx] = 0.f;
    if (idx < Nn) { g_mEnc[idx] = 0x007FFFFFu; g_denom[idx] = 0.f; }
}

__global__ void edge1_kernel() {
    int e = blockIdx.x * blockDim.x + threadIdx.x;
    if (e >= Ee) return;
    int s = g_src[e], d = g_dst[e], t = g_et[e];
    float a = g_qx[d * Rr + t] + g_kx[s * Rr + t];
    a = (a >= 0.f) ? a : 0.2f * a;
    g_alpha[e] = a;
    atomicMax(&g_mEnc[d], encf(a));
}

__global__ void edge2_kernel() {
    int e = blockIdx.x * blockDim.x + threadIdx.x;
    if (e >= Ee) return;
    int d = g_dst[e];
    float m = decf(g_mEnc[d]);
    float ew = expf(g_alpha[e] - m);
    g_alpha[e] = ew;
    atomicAdd(&g_denom[d], ew);
}

__global__ void edge3_kernel() {
    int gtid = blockIdx.x * blockDim.x + threadIdx.x;
    int e = gtid >> 5;
    if (e >= Ee) return;
    int lane = gtid & 31;
    int s = g_src[e], d = g_dst[e], t = g_et[e];
    float w = g_alpha[e] / g_denom[d];
    const float4* row = (const float4*)(g_xr + (size_t)s * RH + t * Hd);
    float4 v = row[lane];
    float4* o = (float4*)(g_acc + (size_t)d * Hd) + lane;
    asm volatile("red.global.add.v4.f32 [%0], {%1, %2, %3, %4};"
                 :: "l"(o), "f"(v.x * w), "f"(v.y * w), "f"(v.z * w), "f"(v.w * w)
                 : "memory");
}

__global__ void bias_relu_kernel(const float* __restrict__ b, float* __restrict__ hout) {
    int idx = blockIdx.x * blockDim.x + threadIdx.x;
    if (idx >= Nn * Hd) return;
    float v = g_acc[idx] + b[idx & 127];
    hout[idx] = v > 0.f ? v : 0.f;
}

// ---------------- final linear + log_softmax ----------------
__global__ __launch_bounds__(256) void final_kernel(const float* __restrict__ h,
                                                    const float* __restrict__ lw,
                                                    const float* __restrict__ lb,
                                                    float* __restrict__ out) {
    __shared__ float sh[8][Hd];
    int tid = threadIdx.x;
    int nodeBase = blockIdx.x * 8;
#pragma unroll
    for (int l = 0; l < 4; l++) {
        int idx = tid + l * 256;
        sh[idx >> 7][idx & 127] = h[(size_t)nodeBase * Hd + idx];
    }
    __syncthreads();
    int w = tid >> 5, lane = tid & 31;
    int n = nodeBase + w;
    float a0 = lb[lane], a1 = lb[lane + 32];
#pragma unroll 16
    for (int f = 0; f < Hd; f++) {
        float hv = sh[w][f];
        a0 = fmaf(hv, lw[f * Cc + lane], a0);
        a1 = fmaf(hv, lw[f * Cc + lane + 32], a1);
    }
    float mx = fmaxf(a0, a1);
#pragma unroll
    for (int o = 16; o; o >>= 1) mx = fmaxf(mx, __shfl_xor_sync(0xffffffffu, mx, o));
    float s = expf(a0 - mx) + expf(a1 - mx);
#pragma unroll
    for (int o = 16; o; o >>= 1) s += __shfl_xor_sync(0xffffffffu, s, o);
    float lse = mx + logf(s);
    out[(size_t)n * Cc + lane]      = a0 - lse;
    out[(size_t)n * Cc + lane + 32] = a1 - lse;
}

// ---------------- host orchestration ----------------
static void run_layer(const float* xin, const float* W, const float* q,
                      const float* k, const float* b, float* hout) {
    wprep_kernel<<<(RH * Fd + 255) / 256, 256>>>(W);
    init_kernel<<<(Nn * Hd + 255) / 256, 256>>>();
    dim3 gg(Rr, (Nn + 127) / 128);
    gemm_mma_kernel<<<gg, 256, SM_TOTAL>>>(xin, q, k);
    edge1_kernel<<<(Ee + 255) / 256, 256>>>();
    edge2_kernel<<<(Ee + 255) / 256, 256>>>();
    edge3_kernel<<<(Ee * 32 + 255) / 256, 256>>>();
    bias_relu_kernel<<<(Nn * Hd + 255) / 256, 256>>>(b, hout);
}

extern "C" void kernel_launch(void* const* d_in, const int* in_sizes, int n_in,
                              void* d_out, int out_size) {
    const float* x     = (const float*)d_in[0];
    const void*  ei    = d_in[1];
    const void*  et    = d_in[2];
    const float* W1    = (const float*)d_in[3];
    const float* q1    = (const float*)d_in[4];
    const float* k1    = (const float*)d_in[5];
    const float* b1    = (const float*)d_in[6];
    const float* W2    = (const float*)d_in[7];
    const float* q2    = (const float*)d_in[8];
    const float* k2    = (const float*)d_in[9];
    const float* b2    = (const float*)d_in[10];
    const float* W3    = (const float*)d_in[11];
    const float* q3    = (const float*)d_in[12];
    const float* k3    = (const float*)d_in[13];
    const float* b3    = (const float*)d_in[14];
    const float* lin_w = (const float*)d_in[15];
    const float* lin_b = (const float*)d_in[16];

    cudaFuncSetAttribute(gemm_mma_kernel,
                         cudaFuncAttributeMaxDynamicSharedMemorySize, SM_TOTAL);

    float *hA = nullptr, *hB = nullptr;
    cudaGetSymbolAddress((void**)&hA, g_hA);
    cudaGetSymbolAddress((void**)&hB, g_hB);

    detect_kernel<<<1, 32>>>((const unsigned*)ei);
    convert_kernel<<<(Ee + 255) / 256, 256>>>(ei, et);

    run_layer(x,  W1, q1, k1, b1, hA);
    run_layer(hA, W2, q2, k2, b2, hB);
    run_layer(hB, W3, q3, k3, b3, hA);

    final_kernel<<<Nn / 8, 256>>>(hA, lin_w, lin_b, (float*)d_out);
}